// round 1
// baseline (speedup 1.0000x reference)
#include <cuda_runtime.h>

// 4 threads cooperate on one query; each scans a contiguous N/4 segment of
// candidates held (negated) in shared memory, then a 4-lane shfl reduction
// with lexicographic (dist, index) compare reproduces jnp.argmin semantics.

#define TPQ   4
#define BLOCK 256

__global__ void __launch_bounds__(BLOCK)
pairwise_linf_argmin_kernel(const float* __restrict__ A,
                            const float* __restrict__ B,
                            float* __restrict__ out,
                            int Q, int N)
{
    extern __shared__ char smem_raw[];
    const int Nseg      = N / TPQ;            // candidates per slot (1024)
    const int segStride = Nseg * 8 + 16;      // bytes; +16B skew kills bank conflicts

    // --- cooperative load: shared holds -B packed as float2, segmented + skewed ---
    const float* __restrict__ Bx = B;
    const float* __restrict__ By = B + N;
    for (int n = threadIdx.x; n < N; n += BLOCK) {
        int s = n / Nseg;
        int j = n - s * Nseg;
        float2* seg = (float2*)(smem_raw + s * segStride);
        seg[j] = make_float2(-Bx[n], -By[n]);
    }
    __syncthreads();

    const int tq = threadIdx.x / TPQ;                 // query within block
    const int s  = threadIdx.x % TPQ;                 // slot (segment)
    const int q  = blockIdx.x * (BLOCK / TPQ) + tq;   // global query
    if (q >= Q) return;

    const float ax = A[2 * q];
    const float ay = A[2 * q + 1];

    const float4* __restrict__ seg = (const float4*)(smem_raw + s * segStride);

    float best = 3.402823466e38f;
    int   bi   = 0;                                   // index within segment

    #pragma unroll 8
    for (int i = 0; i < Nseg / 2; ++i) {
        float4 v = seg[i];                            // two candidates: (-bx,-by),(-bx,-by)
        float dx0 = ax + v.x, dy0 = ay + v.y;
        float d0  = fmaxf(fabsf(dx0), fabsf(dy0));
        float dx1 = ax + v.z, dy1 = ay + v.w;
        float d1  = fmaxf(fabsf(dx1), fabsf(dy1));
        bool p0 = d0 < best;                          // strict < keeps earliest index
        best = p0 ? d0 : best;
        bi   = p0 ? (2 * i)     : bi;
        bool p1 = d1 < best;
        best = p1 ? d1 : best;
        bi   = p1 ? (2 * i + 1) : bi;
    }

    int n_best = s * Nseg + bi;

    // --- reduce over the 4 slots of this query (lanes differ in low 2 bits) ---
    #pragma unroll
    for (int m = 1; m < TPQ; m <<= 1) {
        float od = __shfl_xor_sync(0xffffffffu, best,   m);
        int   on = __shfl_xor_sync(0xffffffffu, n_best, m);
        bool take = (od < best) || (od == best && on < n_best);
        best   = take ? od : best;
        n_best = take ? on : n_best;
    }

    if (s == 0) {
        int sw = n_best / Nseg;
        int j  = n_best - sw * Nseg;
        const float2* segw = (const float2*)(smem_raw + sw * segStride);
        float2 nb = segw[j];                          // -B of winner
        ((float2*)out)[q] = make_float2(ax + nb.x, ay + nb.y);
    }
}

extern "C" void kernel_launch(void* const* d_in, const int* in_sizes, int n_in,
                              void* d_out, int out_size)
{
    const float* A = (const float*)d_in[0];   // [Q, 2]  (Q = batch*L)
    const float* B = (const float*)d_in[1];   // [2, N]
    float*     out = (float*)d_out;           // [Q, 2]

    const int Q = in_sizes[0] / 2;
    const int N = in_sizes[1] / 2;

    const int blocks = (Q * TPQ + BLOCK - 1) / BLOCK;
    const size_t smem = (size_t)TPQ * (size_t)((N / TPQ) * 8 + 16);

    pairwise_linf_argmin_kernel<<<blocks, BLOCK, smem>>>(A, B, out, Q, N);
}

// round 2
// speedup vs baseline: 1.0081x; 1.0081x over previous
#include <cuda_runtime.h>

// 4 threads cooperate on one query; each scans a contiguous N/4 segment of
// candidates held (negated) in shared memory, then a 4-lane shfl reduction
// with lexicographic (dist, index) compare reproduces jnp.argmin semantics.

#define TPQ   4
#define BLOCK 256

__global__ void __launch_bounds__(BLOCK)
pairwise_linf_argmin_kernel(const float* __restrict__ A,
                            const float* __restrict__ B,
                            float* __restrict__ out,
                            int Q, int N)
{
    extern __shared__ char smem_raw[];
    const int Nseg      = N / TPQ;            // candidates per slot (1024)
    const int segStride = Nseg * 8 + 16;      // bytes; +16B skew kills bank conflicts

    // --- cooperative load: shared holds -B packed as float2, segmented + skewed ---
    const float* __restrict__ Bx = B;
    const float* __restrict__ By = B + N;
    for (int n = threadIdx.x; n < N; n += BLOCK) {
        int s = n / Nseg;
        int j = n - s * Nseg;
        float2* seg = (float2*)(smem_raw + s * segStride);
        seg[j] = make_float2(-Bx[n], -By[n]);
    }
    __syncthreads();

    const int tq = threadIdx.x / TPQ;                 // query within block
    const int s  = threadIdx.x % TPQ;                 // slot (segment)
    const int q  = blockIdx.x * (BLOCK / TPQ) + tq;   // global query
    if (q >= Q) return;

    const float ax = A[2 * q];
    const float ay = A[2 * q + 1];

    const float4* __restrict__ seg = (const float4*)(smem_raw + s * segStride);

    float best = 3.402823466e38f;
    int   bi   = 0;                                   // index within segment

    #pragma unroll 8
    for (int i = 0; i < Nseg / 2; ++i) {
        float4 v = seg[i];                            // two candidates: (-bx,-by),(-bx,-by)
        float dx0 = ax + v.x, dy0 = ay + v.y;
        float d0  = fmaxf(fabsf(dx0), fabsf(dy0));
        float dx1 = ax + v.z, dy1 = ay + v.w;
        float d1  = fmaxf(fabsf(dx1), fabsf(dy1));
        bool p0 = d0 < best;                          // strict < keeps earliest index
        best = p0 ? d0 : best;
        bi   = p0 ? (2 * i)     : bi;
        bool p1 = d1 < best;
        best = p1 ? d1 : best;
        bi   = p1 ? (2 * i + 1) : bi;
    }

    int n_best = s * Nseg + bi;

    // --- reduce over the 4 slots of this query (lanes differ in low 2 bits) ---
    #pragma unroll
    for (int m = 1; m < TPQ; m <<= 1) {
        float od = __shfl_xor_sync(0xffffffffu, best,   m);
        int   on = __shfl_xor_sync(0xffffffffu, n_best, m);
        bool take = (od < best) || (od == best && on < n_best);
        best   = take ? od : best;
        n_best = take ? on : n_best;
    }

    if (s == 0) {
        int sw = n_best / Nseg;
        int j  = n_best - sw * Nseg;
        const float2* segw = (const float2*)(smem_raw + sw * segStride);
        float2 nb = segw[j];                          // -B of winner
        ((float2*)out)[q] = make_float2(ax + nb.x, ay + nb.y);
    }
}

extern "C" void kernel_launch(void* const* d_in, const int* in_sizes, int n_in,
                              void* d_out, int out_size)
{
    const float* A = (const float*)d_in[0];   // [Q, 2]  (Q = batch*L)
    const float* B = (const float*)d_in[1];   // [2, N]
    float*     out = (float*)d_out;           // [Q, 2]

    const int Q = in_sizes[0] / 2;
    const int N = in_sizes[1] / 2;

    const int blocks = (Q * TPQ + BLOCK - 1) / BLOCK;
    const size_t smem = (size_t)TPQ * (size_t)((N / TPQ) * 8 + 16);

    pairwise_linf_argmin_kernel<<<blocks, BLOCK, smem>>>(A, B, out, Q, N);
}

// round 3
// speedup vs baseline: 1.0125x; 1.0044x over previous
#include <cuda_runtime.h>

// 4 threads cooperate on one query; each scans a contiguous N/4 segment of
// candidates held (negated) in shared memory, then a 4-lane shfl reduction
// with lexicographic (dist, index) compare reproduces jnp.argmin semantics.

#define TPQ   4
#define BLOCK 256

__global__ void __launch_bounds__(BLOCK)
pairwise_linf_argmin_kernel(const float* __restrict__ A,
                            const float* __restrict__ B,
                            float* __restrict__ out,
                            int Q, int N)
{
    extern __shared__ char smem_raw[];
    const int Nseg      = N / TPQ;            // candidates per slot (1024)
    const int segStride = Nseg * 8 + 16;      // bytes; +16B skew kills bank conflicts

    // --- cooperative load: shared holds -B packed as float2, segmented + skewed ---
    const float* __restrict__ Bx = B;
    const float* __restrict__ By = B + N;
    for (int n = threadIdx.x; n < N; n += BLOCK) {
        int s = n / Nseg;
        int j = n - s * Nseg;
        float2* seg = (float2*)(smem_raw + s * segStride);
        seg[j] = make_float2(-Bx[n], -By[n]);
    }
    __syncthreads();

    const int tq = threadIdx.x / TPQ;                 // query within block
    const int s  = threadIdx.x % TPQ;                 // slot (segment)
    const int q  = blockIdx.x * (BLOCK / TPQ) + tq;   // global query
    if (q >= Q) return;

    const float ax = A[2 * q];
    const float ay = A[2 * q + 1];

    const float4* __restrict__ seg = (const float4*)(smem_raw + s * segStride);

    float best = 3.402823466e38f;
    int   bi   = 0;                                   // index within segment

    #pragma unroll 8
    for (int i = 0; i < Nseg / 2; ++i) {
        float4 v = seg[i];                            // two candidates: (-bx,-by),(-bx,-by)
        float dx0 = ax + v.x, dy0 = ay + v.y;
        float d0  = fmaxf(fabsf(dx0), fabsf(dy0));
        float dx1 = ax + v.z, dy1 = ay + v.w;
        float d1  = fmaxf(fabsf(dx1), fabsf(dy1));
        bool p0 = d0 < best;                          // strict < keeps earliest index
        best = p0 ? d0 : best;
        bi   = p0 ? (2 * i)     : bi;
        bool p1 = d1 < best;
        best = p1 ? d1 : best;
        bi   = p1 ? (2 * i + 1) : bi;
    }

    int n_best = s * Nseg + bi;

    // --- reduce over the 4 slots of this query (lanes differ in low 2 bits) ---
    #pragma unroll
    for (int m = 1; m < TPQ; m <<= 1) {
        float od = __shfl_xor_sync(0xffffffffu, best,   m);
        int   on = __shfl_xor_sync(0xffffffffu, n_best, m);
        bool take = (od < best) || (od == best && on < n_best);
        best   = take ? od : best;
        n_best = take ? on : n_best;
    }

    if (s == 0) {
        int sw = n_best / Nseg;
        int j  = n_best - sw * Nseg;
        const float2* segw = (const float2*)(smem_raw + sw * segStride);
        float2 nb = segw[j];                          // -B of winner
        ((float2*)out)[q] = make_float2(ax + nb.x, ay + nb.y);
    }
}

extern "C" void kernel_launch(void* const* d_in, const int* in_sizes, int n_in,
                              void* d_out, int out_size)
{
    const float* A = (const float*)d_in[0];   // [Q, 2]  (Q = batch*L)
    const float* B = (const float*)d_in[1];   // [2, N]
    float*     out = (float*)d_out;           // [Q, 2]

    const int Q = in_sizes[0] / 2;
    const int N = in_sizes[1] / 2;

    const int blocks = (Q * TPQ + BLOCK - 1) / BLOCK;
    const size_t smem = (size_t)TPQ * (size_t)((N / TPQ) * 8 + 16);

    pairwise_linf_argmin_kernel<<<blocks, BLOCK, smem>>>(A, B, out, Q, N);
}